// round 16
// baseline (speedup 1.0000x reference)
#include <cuda_runtime.h>

// WeightedLoss: mean over 64M elems of (target==1 ? 1-sigmoid(pred) : 0.1)
// 1 - sigmoid(x) = 0.5 - 0.5*tanh(x/2) -> single MUFU.TANH
//
// R15: dynamic chunk scheduling to kill the per-CTA spread tail
// (L2 near/far-die variance makes static grid-stride CTAs finish ~10% apart).
// Chunks of 8 block-iterations; per-chunk partial written to a fixed slot ->
// bitwise-deterministic regardless of which block processed which chunk.
// 256-bit loads (R14: tiny win). Counters re-armed each run for graph replay.

#define NBLOCKS (148 * 8)
#define NTHREADS 256
#define CHUNK_ITERS 8
#define CHUNK_GROUPS (CHUNK_ITERS * NTHREADS)      // v8-groups per chunk = 2048
#define NCHUNKS 4096                                // 8M groups / 2048

__device__ float g_chunk_sum[NCHUNKS];
__device__ unsigned int g_work = 0;     // next chunk to grab
__device__ unsigned int g_arrive = 0;   // blocks done

__device__ __forceinline__ float elem_loss(float p, int t) {
    float s = 0.5f - 0.5f * __tanhf(0.5f * p);   // = 1 - sigmoid(p)
    return (t == 1) ? s : 0.1f;
}

__device__ __forceinline__ void ldg256_f32(const float* a, float* v) {
    asm volatile("ld.global.v8.f32 {%0,%1,%2,%3,%4,%5,%6,%7}, [%8];"
                 : "=f"(v[0]), "=f"(v[1]), "=f"(v[2]), "=f"(v[3]),
                   "=f"(v[4]), "=f"(v[5]), "=f"(v[6]), "=f"(v[7])
                 : "l"(a));
}
__device__ __forceinline__ void ldg256_s32(const int* a, int* v) {
    asm volatile("ld.global.v8.u32 {%0,%1,%2,%3,%4,%5,%6,%7}, [%8];"
                 : "=r"(v[0]), "=r"(v[1]), "=r"(v[2]), "=r"(v[3]),
                   "=r"(v[4]), "=r"(v[5]), "=r"(v[6]), "=r"(v[7])
                 : "l"(a));
}

__device__ __forceinline__ float block_reduce(float acc, float* sw) {
    #pragma unroll
    for (int o = 16; o > 0; o >>= 1)
        acc += __shfl_xor_sync(0xffffffffu, acc, o);
    if ((threadIdx.x & 31) == 0) sw[threadIdx.x >> 5] = acc;
    __syncthreads();
    float v = 0.0f;
    if (threadIdx.x < 32) {
        v = (threadIdx.x < NTHREADS / 32) ? sw[threadIdx.x] : 0.0f;
        #pragma unroll
        for (int o = 4; o > 0; o >>= 1)
            v += __shfl_xor_sync(0xffffffffu, v, o);
    }
    __syncthreads();   // sw reusable next chunk
    return v;          // valid in thread 0
}

__global__ __launch_bounds__(NTHREADS)
void wl_dyn_kernel(const float* __restrict__ pred,
                   const int* __restrict__ tgt,
                   float inv_n,
                   float* __restrict__ out)
{
    __shared__ float sw[NTHREADS / 32];
    __shared__ unsigned int s_chunk;
    __shared__ bool s_last;

    for (;;) {
        if (threadIdx.x == 0)
            s_chunk = atomicAdd(&g_work, 1u);
        __syncthreads();
        unsigned int c = s_chunk;
        if (c >= NCHUNKS) break;

        // process chunk c: fixed elements, fixed order -> deterministic partial
        size_t base = (size_t)c * CHUNK_GROUPS;
        float acc = 0.0f;
        #pragma unroll
        for (int it = 0; it < CHUNK_ITERS; it++) {
            size_t g = base + (size_t)it * NTHREADS + threadIdx.x;
            float p[8];
            int   t[8];
            ldg256_f32(pred + g * 8, p);
            ldg256_s32(tgt  + g * 8, t);
            #pragma unroll
            for (int k = 0; k < 8; k++)
                acc += elem_loss(p[k], t[k]);
        }
        float v = block_reduce(acc, sw);
        if (threadIdx.x == 0)
            g_chunk_sum[c] = v;
        __syncthreads();
    }

    // arrive; last block does the final fixed-order reduction
    if (threadIdx.x == 0) {
        __threadfence();
        unsigned int prev = atomicAdd(&g_arrive, 1u);
        s_last = (prev == (unsigned int)(gridDim.x - 1));
    }
    __syncthreads();

    if (s_last) {
        float a = 0.0f;
        for (int j = threadIdx.x; j < NCHUNKS; j += NTHREADS)
            a += g_chunk_sum[j];   // 16 per thread, fixed order
        float v = block_reduce(a, sw);
        if (threadIdx.x == 0) {
            out[0] = v * inv_n;
            __threadfence();
            g_work = 0;            // re-arm for next graph replay
            g_arrive = 0;
        }
    }
}

extern "C" void kernel_launch(void* const* d_in, const int* in_sizes, int n_in,
                              void* d_out, int out_size)
{
    const float* pred = (const float*)d_in[0];
    const int*   tgt  = (const int*)d_in[1];
    float*       out  = (float*)d_out;
    const int n = in_sizes[0];   // 64M = NCHUNKS * CHUNK_GROUPS * 8 exactly

    wl_dyn_kernel<<<NBLOCKS, NTHREADS>>>(pred, tgt, 1.0f / (float)n, out);
}